// round 5
// baseline (speedup 1.0000x reference)
#include <cuda_runtime.h>

#define P_DIM 512
#define Q_DIM 64
#define B_DIM 16
#define E_DIM 256
#define H_DIM 256
#define O_DIM 256

// ---------------- scratch (static __device__, no allocation) ----------------
__device__ float g_Wp[P_DIM * B_DIM * H_DIM];          // (P,B,H)
__device__ float g_Wq[Q_DIM * B_DIM * H_DIM];          // (Q,B,H)
__device__ float g_gcat[P_DIM * B_DIM * 2 * E_DIM];    // (P,B,2E) = [passage | c]
__device__ float g_cg[P_DIM * B_DIM * E_DIM];          // c_gated
__device__ float g_gi[P_DIM * B_DIM * 3 * O_DIM];      // gi = x@w_ih^T + b_ih

// ---------------- math helpers ----------------
__device__ __forceinline__ float fast_tanh(float x) {
    float e = __expf(2.f * x);
    return 1.f - __fdividef(2.f, e + 1.f);
}
__device__ __forceinline__ float fast_sigmoid(float x) {
    return __fdividef(1.f, 1.f + __expf(-x));
}
__device__ __forceinline__ unsigned smem_u32(const void* p) {
    return (unsigned)__cvta_generic_to_shared(p);
}
__device__ __forceinline__ void fma_f32x2(unsigned long long& acc,
                                          unsigned long long a,
                                          unsigned long long b) {
    asm("fma.rn.f32x2 %0, %1, %2, %0;" : "+l"(acc) : "l"(a), "l"(b));
}

// ---------------- generic fp32 GEMM: C[M,N] = epi(A[M,K] @ W[N,K]^T) ----------------
// MODE 0: raw    MODE 1: + bias[n]    MODE 2: sigmoid(acc) * aux[row*512 + 256 + n]
template <int MODE>
__global__ __launch_bounds__(256) void gemm_kernel(
    const float* __restrict__ A, const float* __restrict__ W,
    const float* __restrict__ bias, const float* __restrict__ aux,
    float* __restrict__ C, int M, int N, int K)
{
    __shared__ float As[32 * 68];   // [k][m], padded stride 68
    __shared__ float Ws[32 * 68];   // [k][n]

    const int tid = threadIdx.x;
    const int m0 = blockIdx.x * 64;
    const int n0 = blockIdx.y * 64;
    const int tm = tid >> 4;   // 0..15
    const int tn = tid & 15;   // 0..15
    const int K4 = K >> 2;

    float acc[4][4];
#pragma unroll
    for (int i = 0; i < 4; i++)
#pragma unroll
        for (int j = 0; j < 4; j++) acc[i][j] = 0.f;

    const float4* A4 = (const float4*)A;
    const float4* W4 = (const float4*)W;

    for (int k0 = 0; k0 < K; k0 += 32) {
#pragma unroll
        for (int t = 0; t < 2; t++) {
            int idx = tid + t * 256;          // 0..511
            int r = idx >> 3;                 // 0..63
            int c4 = idx & 7;                 // 0..7
            float4 va = A4[(long)(m0 + r) * K4 + (k0 >> 2) + c4];
            float4 vw = W4[(long)(n0 + r) * K4 + (k0 >> 2) + c4];
            int kk = c4 * 4;
            As[(kk + 0) * 68 + r] = va.x; As[(kk + 1) * 68 + r] = va.y;
            As[(kk + 2) * 68 + r] = va.z; As[(kk + 3) * 68 + r] = va.w;
            Ws[(kk + 0) * 68 + r] = vw.x; Ws[(kk + 1) * 68 + r] = vw.y;
            Ws[(kk + 2) * 68 + r] = vw.z; Ws[(kk + 3) * 68 + r] = vw.w;
        }
        __syncthreads();

        const float4* As4 = (const float4*)As;
        const float4* Ws4 = (const float4*)Ws;
#pragma unroll
        for (int k = 0; k < 32; k++) {
            float4 a = As4[k * 17 + tm];
            float4 w = Ws4[k * 17 + tn];
            acc[0][0] += a.x * w.x; acc[0][1] += a.x * w.y; acc[0][2] += a.x * w.z; acc[0][3] += a.x * w.w;
            acc[1][0] += a.y * w.x; acc[1][1] += a.y * w.y; acc[1][2] += a.y * w.z; acc[1][3] += a.y * w.w;
            acc[2][0] += a.z * w.x; acc[2][1] += a.z * w.y; acc[2][2] += a.z * w.z; acc[2][3] += a.z * w.w;
            acc[3][0] += a.w * w.x; acc[3][1] += a.w * w.y; acc[3][2] += a.w * w.z; acc[3][3] += a.w * w.w;
        }
        __syncthreads();
    }

#pragma unroll
    for (int i = 0; i < 4; i++) {
        int row = m0 + tm * 4 + i;
        int col = n0 + tn * 4;
        float4 o;
        if (MODE == 0) {
            o = make_float4(acc[i][0], acc[i][1], acc[i][2], acc[i][3]);
        } else if (MODE == 1) {
            o = make_float4(acc[i][0] + bias[col + 0], acc[i][1] + bias[col + 1],
                            acc[i][2] + bias[col + 2], acc[i][3] + bias[col + 3]);
        } else {
            float4 g = *(const float4*)(aux + (long)row * 512 + 256 + col);
            o = make_float4(fast_sigmoid(acc[i][0]) * g.x, fast_sigmoid(acc[i][1]) * g.y,
                            fast_sigmoid(acc[i][2]) * g.z, fast_sigmoid(acc[i][3]) * g.w);
        }
        *(float4*)(&C[(long)row * N + col]) = o;
    }
}

// ---------------- fused attention: scores -> softmax -> context -> concat ----------------
__global__ __launch_bounds__(256) void attn_kernel(
    const float* __restrict__ question, const float* __restrict__ passage,
    const float* __restrict__ v)
{
    __shared__ float wp[256];
    __shared__ float vv[256];
    __shared__ float sc[64];

    const int p = blockIdx.x;
    const int b = blockIdx.y;
    const int tid = threadIdx.x;
    const int w = tid >> 5, l = tid & 31;

    wp[tid] = g_Wp[((long)p * B_DIM + b) * H_DIM + tid];
    vv[tid] = v[tid];
    __syncthreads();

#pragma unroll
    for (int qi = 0; qi < 8; qi++) {
        int q = w * 8 + qi;
        const float* wq = &g_Wq[((long)q * B_DIM + b) * H_DIM];
        float acc = 0.f;
#pragma unroll
        for (int j = 0; j < 8; j++) {
            int h = l + 32 * j;
            acc += vv[h] * fast_tanh(wq[h] + wp[h]);
        }
#pragma unroll
        for (int s = 16; s > 0; s >>= 1) acc += __shfl_xor_sync(0xffffffffu, acc, s);
        if (l == 0) sc[q] = acc;
    }
    __syncthreads();

    if (w == 0) {
        float s0 = sc[l], s1 = sc[32 + l];
        float m = fmaxf(s0, s1);
#pragma unroll
        for (int s = 16; s > 0; s >>= 1) m = fmaxf(m, __shfl_xor_sync(0xffffffffu, m, s));
        float e0 = __expf(s0 - m), e1 = __expf(s1 - m);
        float sum = e0 + e1;
#pragma unroll
        for (int s = 16; s > 0; s >>= 1) sum += __shfl_xor_sync(0xffffffffu, sum, s);
        float inv = __fdividef(1.f, sum);
        sc[l] = e0 * inv;
        sc[32 + l] = e1 * inv;
    }
    __syncthreads();

    float acc = 0.f;
#pragma unroll
    for (int q = 0; q < 64; q++)
        acc += sc[q] * question[((long)q * B_DIM + b) * E_DIM + tid];

    float* gr = &g_gcat[((long)p * B_DIM + b) * 2 * E_DIM];
    gr[256 + tid] = acc;
    gr[tid] = passage[((long)p * B_DIM + b) * E_DIM + tid];
}

// ---------------- GRU v5: warp-local step, zero block syncs in loop ---------------
// 256 threads: thread (o = tid>>3, s = tid&7) owns gate rows r/z/n of output o,
// K-slice [32s, 32s+32). Shuffle-reduce over the 8 s-lanes gives gh_r/z/n to the
// whole group; gates+publish run per-warp (8 warps x 4 outputs in parallel).
// h travels as (counter<<32 | f32bits) relaxed u64 DSMEM stores (fence-free,
// single-copy atomic); consumers validate a slice via counter-sum. gi is
// register-pipelined one full step ahead.
__global__ void __cluster_dims__(8, 1, 1) __launch_bounds__(256, 1)
gru_kernel(const float* __restrict__ gi, const float* __restrict__ w_hh,
           const float* __restrict__ b_hh, float* __restrict__ out)
{
    // hb64[buf][slice s][34]: 32 elements + 2 pad (272B stride -> conflict-free)
    __shared__ __align__(16) unsigned long long hb64[2][8 * 34];

    const int tid = threadIdx.x;
    const int lane = tid & 31;
    const int b = blockIdx.x >> 3;     // batch
    const int rank = blockIdx.x & 7;   // cluster rank
    const int o = tid >> 3;            // output 0..31 (within this CTA's chunk)
    const int s = tid & 7;             // K-slice 0..7 (32 floats each)
    const int og = rank * 32 + o;      // global output index
    const int base = lane & 24;        // first lane of this thread's o-group

    // ---- preload weights: rows {g*256 + og : g=0,1,2}, cols [32s, 32s+32) ----
    unsigned long long wr[16], wz[16], wn[16];
    {
        const float4* r4 = (const float4*)(w_hh + (long)(0 * 256 + og) * 256 + s * 32);
        const float4* z4 = (const float4*)(w_hh + (long)(1 * 256 + og) * 256 + s * 32);
        const float4* n4 = (const float4*)(w_hh + (long)(2 * 256 + og) * 256 + s * 32);
#pragma unroll
        for (int i = 0; i < 8; i++) {
            float4 tr = r4[i], tz = z4[i], tn = n4[i];
            asm("mov.b64 %0, {%1,%2};" : "=l"(wr[2*i])   : "f"(tr.x), "f"(tr.y));
            asm("mov.b64 %0, {%1,%2};" : "=l"(wr[2*i+1]) : "f"(tr.z), "f"(tr.w));
            asm("mov.b64 %0, {%1,%2};" : "=l"(wz[2*i])   : "f"(tz.x), "f"(tz.y));
            asm("mov.b64 %0, {%1,%2};" : "=l"(wz[2*i+1]) : "f"(tz.z), "f"(tz.w));
            asm("mov.b64 %0, {%1,%2};" : "=l"(wn[2*i])   : "f"(tn.x), "f"(tn.y));
            asm("mov.b64 %0, {%1,%2};" : "=l"(wn[2*i+1]) : "f"(tn.z), "f"(tn.w));
        }
    }
    const float b_r = b_hh[0 * 256 + og];
    const float b_z = b_hh[1 * 256 + og];
    const float b_n = b_hh[2 * 256 + og];

    for (int i = tid; i < 2 * 8 * 34; i += 256) ((unsigned long long*)hb64)[i] = 0ull;

    // precompute remote slot addresses for this thread's output (buffer 0)
    unsigned peerAddr[8];
    {
        unsigned laddr = smem_u32(&hb64[0][rank * 34 + o]);
#pragma unroll
        for (int c = 0; c < 8; c++)
            asm("mapa.shared::cluster.u32 %0, %1, %2;" : "=r"(peerAddr[c]) : "r"(laddr), "r"(c));
    }
    __syncthreads();
    asm volatile("barrier.cluster.arrive.aligned;" ::: "memory");
    asm volatile("barrier.cluster.wait.aligned;" ::: "memory");

    const unsigned hbBase = smem_u32(&hb64[0][0]);
    const unsigned holdAddr = smem_u32(&hb64[0][rank * 34 + o]);

    // gi pipeline: lane s in {0,1,2} carries gi for gate s of output o, one step ahead
    float gcur = 0.f;
    if (s < 3) gcur = gi[((long)0 * B_DIM + b) * 768 + s * 256 + og];

    for (int p = 0; p < P_DIM; p++) {
        const int cur = p & 1;
        const int nxt = cur ^ 1;

        // issue next step's gi load immediately (full step of latency cover)
        float gnext = 0.f;
        if (s < 3 && p + 1 < P_DIM)
            gnext = gi[((long)(p + 1) * B_DIM + b) * 768 + s * 256 + og];

        // ---- poll: this thread's 32-element slice of hb[cur] must be fresh ----
        const unsigned sbase = hbBase + (unsigned)(cur * 2176 + s * 272);
        const unsigned tgt = 32u * (unsigned)p;
        unsigned long long hx[16], hy[16];
        for (;;) {
            unsigned sum = 0;
#pragma unroll
            for (int i = 0; i < 16; i++) {
                asm volatile("ld.volatile.shared.v2.u64 {%0,%1}, [%2];"
                             : "=l"(hx[i]), "=l"(hy[i]) : "r"(sbase + (unsigned)(i * 16)));
                sum += (unsigned)(hx[i] >> 32) + (unsigned)(hy[i] >> 32);
            }
            if (sum == tgt) break;
        }

        // ---- 48 packed FMAs: 3 gate rows x 16 f32x2 ----
        unsigned long long ar = 0ull, az = 0ull, an = 0ull;
#pragma unroll
        for (int i = 0; i < 16; i++) {
            float v0 = __uint_as_float((unsigned)hx[i]);
            float v1 = __uint_as_float((unsigned)hy[i]);
            unsigned long long hp;
            asm("mov.b64 %0, {%1,%2};" : "=l"(hp) : "f"(v0), "f"(v1));
            fma_f32x2(ar, wr[i], hp);
            fma_f32x2(az, wz[i], hp);
            fma_f32x2(an, wn[i], hp);
        }
        float r0, r1, z0, z1, n0, n1;
        asm("mov.b64 {%0,%1}, %2;" : "=f"(r0), "=f"(r1) : "l"(ar));
        asm("mov.b64 {%0,%1}, %2;" : "=f"(z0), "=f"(z1) : "l"(az));
        asm("mov.b64 {%0,%1}, %2;" : "=f"(n0), "=f"(n1) : "l"(an));
        float ghr = r0 + r1, ghz = z0 + z1, ghn = n0 + n1;
        // reduce over the 8 s-lanes (intra-warp; also converges the warp)
#pragma unroll
        for (int d = 1; d < 8; d <<= 1) {
            ghr += __shfl_xor_sync(0xffffffffu, ghr, d);
            ghz += __shfl_xor_sync(0xffffffffu, ghz, d);
            ghn += __shfl_xor_sync(0xffffffffu, ghn, d);
        }

        // gather gi (r,z,n) from lanes base, base+1, base+2
        float gir = __shfl_sync(0xffffffffu, gcur, base);
        float giz = __shfl_sync(0xffffffffu, gcur, base + 1);
        float gin = __shfl_sync(0xffffffffu, gcur, base + 2);

        // gates (computed redundantly by all 8 lanes; owner publishes)
        float r = fast_sigmoid(gir + ghr + b_r);
        float z = fast_sigmoid(giz + ghz + b_z);
        float n = fast_tanh(gin + r * (ghn + b_n));
        unsigned long long holdPk;
        asm volatile("ld.shared.u64 %0, [%1];" : "=l"(holdPk)
                     : "r"(holdAddr + (unsigned)(cur * 2176)));
        float hold = __uint_as_float((unsigned)holdPk);
        float hnew = (1.f - z) * n + z * hold;

        if (s == 0) {
            out[((long)p * B_DIM + b) * O_DIM + og] = hnew;
            if (p < P_DIM - 1) {
                unsigned long long pv =
                    (((unsigned long long)(unsigned)(p + 1)) << 32) |
                    (unsigned long long)__float_as_uint(hnew);
                const unsigned boff = (unsigned)(nxt * 2176);
#pragma unroll
                for (int c = 0; c < 8; c++)
                    asm volatile("st.relaxed.cluster.shared::cluster.u64 [%0], %1;"
                                 :: "r"(peerAddr[c] + boff), "l"(pv) : "memory");
            }
        }
        gcur = gnext;
    }
}

// ---------------- launch ----------------
extern "C" void kernel_launch(void* const* d_in, const int* in_sizes, int n_in,
                              void* d_out, int out_size)
{
    const float* passage  = (const float*)d_in[0];
    const float* question = (const float*)d_in[1];
    const float* Wuq      = (const float*)d_in[2];
    const float* Wup      = (const float*)d_in[3];
    const float* v        = (const float*)d_in[4];
    const float* Wg       = (const float*)d_in[5];
    const float* w_ih     = (const float*)d_in[6];
    const float* w_hh     = (const float*)d_in[7];
    const float* b_ih     = (const float*)d_in[8];
    const float* b_hh     = (const float*)d_in[9];
    float* out = (float*)d_out;

    void *pWp, *pWq, *pGcat, *pCg, *pGi;
    cudaGetSymbolAddress(&pWp, g_Wp);
    cudaGetSymbolAddress(&pWq, g_Wq);
    cudaGetSymbolAddress(&pGcat, g_gcat);
    cudaGetSymbolAddress(&pCg, g_cg);
    cudaGetSymbolAddress(&pGi, g_gi);

    dim3 blk(256);

    gemm_kernel<0><<<dim3(8192 / 64, 256 / 64), blk>>>(
        passage, Wup, nullptr, nullptr, (float*)pWp, 8192, 256, 256);
    gemm_kernel<0><<<dim3(1024 / 64, 256 / 64), blk>>>(
        question, Wuq, nullptr, nullptr, (float*)pWq, 1024, 256, 256);
    attn_kernel<<<dim3(P_DIM, B_DIM), blk>>>(question, passage, v);
    gemm_kernel<2><<<dim3(8192 / 64, 256 / 64), blk>>>(
        (const float*)pGcat, Wg + 256 * 512, nullptr, (const float*)pGcat,
        (float*)pCg, 8192, 256, 512);
    gemm_kernel<1><<<dim3(8192 / 64, 768 / 64), blk>>>(
        (const float*)pCg, w_ih, b_ih, nullptr, (float*)pGi, 8192, 768, 256);
    gru_kernel<<<128, 256>>>((const float*)pGi, w_hh, b_hh, out);
}

// round 6
// speedup vs baseline: 2.2962x; 2.2962x over previous
#include <cuda_runtime.h>

#define P_DIM 512
#define Q_DIM 64
#define B_DIM 16
#define E_DIM 256
#define H_DIM 256
#define O_DIM 256

// ---------------- scratch (static __device__, no allocation) ----------------
__device__ float g_Wp[P_DIM * B_DIM * H_DIM];          // (P,B,H)
__device__ float g_Wq[Q_DIM * B_DIM * H_DIM];          // (Q,B,H)
__device__ float g_gcat[P_DIM * B_DIM * 2 * E_DIM];    // (P,B,2E) = [passage | c]
__device__ float g_cg[P_DIM * B_DIM * E_DIM];          // c_gated
__device__ float g_gi[P_DIM * B_DIM * 3 * O_DIM];      // gi = x@w_ih^T + b_ih

// ---------------- math helpers ----------------
__device__ __forceinline__ float fast_tanh(float x) {
    float e = __expf(2.f * x);
    return 1.f - __fdividef(2.f, e + 1.f);
}
__device__ __forceinline__ float fast_sigmoid(float x) {
    return __fdividef(1.f, 1.f + __expf(-x));
}
__device__ __forceinline__ unsigned smem_u32(const void* p) {
    return (unsigned)__cvta_generic_to_shared(p);
}
__device__ __forceinline__ void fma_f32x2(unsigned long long& acc,
                                          unsigned long long a,
                                          unsigned long long b) {
    asm("fma.rn.f32x2 %0, %1, %2, %0;" : "+l"(acc) : "l"(a), "l"(b));
}

// ---------------- generic fp32 GEMM: C[M,N] = epi(A[M,K] @ W[N,K]^T) ----------------
// MODE 0: raw    MODE 1: + bias[n]    MODE 2: sigmoid(acc) * aux[row*512 + 256 + n]
template <int MODE>
__global__ __launch_bounds__(256) void gemm_kernel(
    const float* __restrict__ A, const float* __restrict__ W,
    const float* __restrict__ bias, const float* __restrict__ aux,
    float* __restrict__ C, int M, int N, int K)
{
    __shared__ float As[32 * 68];   // [k][m], padded stride 68
    __shared__ float Ws[32 * 68];   // [k][n]

    const int tid = threadIdx.x;
    const int m0 = blockIdx.x * 64;
    const int n0 = blockIdx.y * 64;
    const int tm = tid >> 4;   // 0..15
    const int tn = tid & 15;   // 0..15
    const int K4 = K >> 2;

    float acc[4][4];
#pragma unroll
    for (int i = 0; i < 4; i++)
#pragma unroll
        for (int j = 0; j < 4; j++) acc[i][j] = 0.f;

    const float4* A4 = (const float4*)A;
    const float4* W4 = (const float4*)W;

    for (int k0 = 0; k0 < K; k0 += 32) {
#pragma unroll
        for (int t = 0; t < 2; t++) {
            int idx = tid + t * 256;          // 0..511
            int r = idx >> 3;                 // 0..63
            int c4 = idx & 7;                 // 0..7
            float4 va = A4[(long)(m0 + r) * K4 + (k0 >> 2) + c4];
            float4 vw = W4[(long)(n0 + r) * K4 + (k0 >> 2) + c4];
            int kk = c4 * 4;
            As[(kk + 0) * 68 + r] = va.x; As[(kk + 1) * 68 + r] = va.y;
            As[(kk + 2) * 68 + r] = va.z; As[(kk + 3) * 68 + r] = va.w;
            Ws[(kk + 0) * 68 + r] = vw.x; Ws[(kk + 1) * 68 + r] = vw.y;
            Ws[(kk + 2) * 68 + r] = vw.z; Ws[(kk + 3) * 68 + r] = vw.w;
        }
        __syncthreads();

        const float4* As4 = (const float4*)As;
        const float4* Ws4 = (const float4*)Ws;
#pragma unroll
        for (int k = 0; k < 32; k++) {
            float4 a = As4[k * 17 + tm];
            float4 w = Ws4[k * 17 + tn];
            acc[0][0] += a.x * w.x; acc[0][1] += a.x * w.y; acc[0][2] += a.x * w.z; acc[0][3] += a.x * w.w;
            acc[1][0] += a.y * w.x; acc[1][1] += a.y * w.y; acc[1][2] += a.y * w.z; acc[1][3] += a.y * w.w;
            acc[2][0] += a.z * w.x; acc[2][1] += a.z * w.y; acc[2][2] += a.z * w.z; acc[2][3] += a.z * w.w;
            acc[3][0] += a.w * w.x; acc[3][1] += a.w * w.y; acc[3][2] += a.w * w.z; acc[3][3] += a.w * w.w;
        }
        __syncthreads();
    }

#pragma unroll
    for (int i = 0; i < 4; i++) {
        int row = m0 + tm * 4 + i;
        int col = n0 + tn * 4;
        float4 o;
        if (MODE == 0) {
            o = make_float4(acc[i][0], acc[i][1], acc[i][2], acc[i][3]);
        } else if (MODE == 1) {
            o = make_float4(acc[i][0] + bias[col + 0], acc[i][1] + bias[col + 1],
                            acc[i][2] + bias[col + 2], acc[i][3] + bias[col + 3]);
        } else {
            float4 g = *(const float4*)(aux + (long)row * 512 + 256 + col);
            o = make_float4(fast_sigmoid(acc[i][0]) * g.x, fast_sigmoid(acc[i][1]) * g.y,
                            fast_sigmoid(acc[i][2]) * g.z, fast_sigmoid(acc[i][3]) * g.w);
        }
        *(float4*)(&C[(long)row * N + col]) = o;
    }
}

// ---------------- fused attention: scores -> softmax -> context -> concat ----------------
__global__ __launch_bounds__(256) void attn_kernel(
    const float* __restrict__ question, const float* __restrict__ passage,
    const float* __restrict__ v)
{
    __shared__ float wp[256];
    __shared__ float vv[256];
    __shared__ float sc[64];

    const int p = blockIdx.x;
    const int b = blockIdx.y;
    const int tid = threadIdx.x;
    const int w = tid >> 5, l = tid & 31;

    wp[tid] = g_Wp[((long)p * B_DIM + b) * H_DIM + tid];
    vv[tid] = v[tid];
    __syncthreads();

#pragma unroll
    for (int qi = 0; qi < 8; qi++) {
        int q = w * 8 + qi;
        const float* wq = &g_Wq[((long)q * B_DIM + b) * H_DIM];
        float acc = 0.f;
#pragma unroll
        for (int j = 0; j < 8; j++) {
            int h = l + 32 * j;
            acc += vv[h] * fast_tanh(wq[h] + wp[h]);
        }
#pragma unroll
        for (int s = 16; s > 0; s >>= 1) acc += __shfl_xor_sync(0xffffffffu, acc, s);
        if (l == 0) sc[q] = acc;
    }
    __syncthreads();

    if (w == 0) {
        float s0 = sc[l], s1 = sc[32 + l];
        float m = fmaxf(s0, s1);
#pragma unroll
        for (int s = 16; s > 0; s >>= 1) m = fmaxf(m, __shfl_xor_sync(0xffffffffu, m, s));
        float e0 = __expf(s0 - m), e1 = __expf(s1 - m);
        float sum = e0 + e1;
#pragma unroll
        for (int s = 16; s > 0; s >>= 1) sum += __shfl_xor_sync(0xffffffffu, sum, s);
        float inv = __fdividef(1.f, sum);
        sc[l] = e0 * inv;
        sc[32 + l] = e1 * inv;
    }
    __syncthreads();

    float acc = 0.f;
#pragma unroll
    for (int q = 0; q < 64; q++)
        acc += sc[q] * question[((long)q * B_DIM + b) * E_DIM + tid];

    float* gr = &g_gcat[((long)p * B_DIM + b) * 2 * E_DIM];
    gr[256 + tid] = acc;
    gr[tid] = passage[((long)p * B_DIM + b) * E_DIM + tid];
}

// ---------------- GRU v6: broadcast-LDS GEMV, one bar/step, fence-free DSMEM ------
// 256 thr/CTA, 8-CTA cluster per batch. Warp w = K-slice [32w,32w+32); lane l
// owns output og=rank*32+l (rows r/z/n, 96 weights in regs as 48 f32x2).
// h is read via LDS.128 with ALL lanes at the same address (broadcast, N=1) --
// unique traffic 1KB/step instead of 96KB. Cross-warp reduce via part[8][3][32]
// (conflict-free), ONE __syncthreads per step. h travels as (cnt<<32|f32bits)
// relaxed u64 DSMEM stores; poll via counter check (no fence -> no L1 flush).
__global__ void __cluster_dims__(8, 1, 1) __launch_bounds__(256, 1)
gru_kernel(const float* __restrict__ gi, const float* __restrict__ w_hh,
           const float* __restrict__ b_hh, float* __restrict__ out)
{
    __shared__ __align__(16) unsigned long long hb64[2][260];  // 256 slots + 4 pad, 2080B stride
    __shared__ float part[8][3][32];                           // [srcWarp][gate][output]

    const int tid = threadIdx.x;
    const int w = tid >> 5;            // K-slice warp 0..7
    const int l = tid & 31;            // output lane
    const int b = blockIdx.x >> 3;     // batch
    const int rank = blockIdx.x & 7;   // cluster rank
    const int og = rank * 32 + l;      // global output index

    // ---- weights: rows {g*256+og}, cols [32w, 32w+32) -> 48 f32x2 regs ----
    unsigned long long wg2[3][16];
#pragma unroll
    for (int g = 0; g < 3; g++) {
        const float4* p4 = (const float4*)(w_hh + (long)(g * 256 + og) * 256 + w * 32);
#pragma unroll
        for (int i = 0; i < 8; i++) {
            float4 t = p4[i];
            asm("mov.b64 %0, {%1,%2};" : "=l"(wg2[g][2*i])   : "f"(t.x), "f"(t.y));
            asm("mov.b64 %0, {%1,%2};" : "=l"(wg2[g][2*i+1]) : "f"(t.z), "f"(t.w));
        }
    }
    const float b_r = b_hh[0 * 256 + og];
    const float b_z = b_hh[1 * 256 + og];
    const float b_n = b_hh[2 * 256 + og];

    for (int i = tid; i < 2 * 260; i += 256) ((unsigned long long*)hb64)[i] = 0ull;

    // remote slot addresses for this lane's output, buffer 0
    unsigned peerAddr[8];
    {
        unsigned laddr = smem_u32(&hb64[0][rank * 32 + l]);
#pragma unroll
        for (int c = 0; c < 8; c++)
            asm("mapa.shared::cluster.u32 %0, %1, %2;" : "=r"(peerAddr[c]) : "r"(laddr), "r"(c));
    }
    __syncthreads();
    asm volatile("barrier.cluster.arrive.aligned;" ::: "memory");
    asm volatile("barrier.cluster.wait.aligned;" ::: "memory");

    const unsigned hbBase = smem_u32(&hb64[0][0]);

    // gi pipeline (warp 0 only), one step ahead
    float gr_c = 0.f, gz_c = 0.f, gn_c = 0.f;
    if (w == 0) {
        long base = ((long)0 * B_DIM + b) * 768 + og;
        gr_c = gi[base]; gz_c = gi[base + 256]; gn_c = gi[base + 512];
    }

    for (int p = 0; p < P_DIM; p++) {
        const int cur = p & 1;
        const int nxt = cur ^ 1;

        float gr_n = 0.f, gz_n = 0.f, gn_n = 0.f;
        if (w == 0 && p + 1 < P_DIM) {
            long base = ((long)(p + 1) * B_DIM + b) * 768 + og;
            gr_n = gi[base]; gz_n = gi[base + 256]; gn_n = gi[base + 512];
        }

        // ---- poll: counters of my K-slice must reach p (per-lane element) ----
        {
            const unsigned sa = hbBase + (unsigned)(cur * 2080 + (32 * w + l) * 8);
            for (;;) {
                unsigned long long v;
                asm volatile("ld.volatile.shared.u64 %0, [%1];" : "=l"(v) : "r"(sa));
                if (__ballot_sync(0xffffffffu, (unsigned)(v >> 32) >= (unsigned)p)
                    == 0xffffffffu) break;
            }
        }

        // ---- GEMV: 16 broadcast LDS.128 (2 h-elements each) + 3 FFMA2 ----
        const unsigned pairBase = hbBase + (unsigned)(cur * 2080 + 32 * w * 8);
        unsigned long long ar = 0ull, az = 0ull, an = 0ull;
#pragma unroll
        for (int j = 0; j < 16; j++) {
            unsigned long long x, y;   // (cnt|h[2j]), (cnt|h[2j+1]) -- ALL lanes same addr
            asm volatile("ld.shared.v2.u64 {%0,%1}, [%2];"
                         : "=l"(x), "=l"(y) : "r"(pairBase + (unsigned)(j * 16)));
            float v0 = __uint_as_float((unsigned)x);
            float v1 = __uint_as_float((unsigned)y);
            unsigned long long hp;
            asm("mov.b64 %0, {%1,%2};" : "=l"(hp) : "f"(v0), "f"(v1));
            fma_f32x2(ar, wg2[0][j], hp);
            fma_f32x2(az, wg2[1][j], hp);
            fma_f32x2(an, wg2[2][j], hp);
        }
        {
            float x0, x1;
            asm("mov.b64 {%0,%1}, %2;" : "=f"(x0), "=f"(x1) : "l"(ar));
            part[w][0][l] = x0 + x1;
            asm("mov.b64 {%0,%1}, %2;" : "=f"(x0), "=f"(x1) : "l"(az));
            part[w][1][l] = x0 + x1;
            asm("mov.b64 {%0,%1}, %2;" : "=f"(x0), "=f"(x1) : "l"(an));
            part[w][2][l] = x0 + x1;
        }
        __syncthreads();   // partials visible; ONLY barrier in the loop

        if (w == 0) {
            float sr = b_r, sz = b_z, sn = b_n;
#pragma unroll
            for (int ww = 0; ww < 8; ww++) {
                sr += part[ww][0][l];
                sz += part[ww][1][l];
                sn += part[ww][2][l];
            }
            float r = fast_sigmoid(gr_c + sr);
            float z = fast_sigmoid(gz_c + sz);
            float n = fast_tanh(gn_c + r * sn);
            float hold = __uint_as_float((unsigned)hb64[cur][rank * 32 + l]);
            float hnew = (1.f - z) * n + z * hold;
            out[((long)p * B_DIM + b) * O_DIM + og] = hnew;

            if (p < P_DIM - 1) {
                unsigned long long pv =
                    (((unsigned long long)(unsigned)(p + 1)) << 32) |
                    (unsigned long long)__float_as_uint(hnew);
                const unsigned boff = (unsigned)(nxt * 2080);
#pragma unroll
                for (int c = 0; c < 8; c++)
                    asm volatile("st.relaxed.cluster.shared::cluster.u64 [%0], %1;"
                                 :: "r"(peerAddr[c] + boff), "l"(pv) : "memory");
            }
        }
        gr_c = gr_n; gz_c = gz_n; gn_c = gn_n;
    }
}

// ---------------- launch ----------------
extern "C" void kernel_launch(void* const* d_in, const int* in_sizes, int n_in,
                              void* d_out, int out_size)
{
    const float* passage  = (const float*)d_in[0];
    const float* question = (const float*)d_in[1];
    const float* Wuq      = (const float*)d_in[2];
    const float* Wup      = (const float*)d_in[3];
    const float* v        = (const float*)d_in[4];
    const float* Wg       = (const float*)d_in[5];
    const float* w_ih     = (const float*)d_in[6];
    const float* w_hh     = (const float*)d_in[7];
    const float* b_ih     = (const float*)d_in[8];
    const float* b_hh     = (const float*)d_in[9];
    float* out = (float*)d_out;

    void *pWp, *pWq, *pGcat, *pCg, *pGi;
    cudaGetSymbolAddress(&pWp, g_Wp);
    cudaGetSymbolAddress(&pWq, g_Wq);
    cudaGetSymbolAddress(&pGcat, g_gcat);
    cudaGetSymbolAddress(&pCg, g_cg);
    cudaGetSymbolAddress(&pGi, g_gi);

    dim3 blk(256);

    gemm_kernel<0><<<dim3(8192 / 64, 256 / 64), blk>>>(
        passage, Wup, nullptr, nullptr, (float*)pWp, 8192, 256, 256);
    gemm_kernel<0><<<dim3(1024 / 64, 256 / 64), blk>>>(
        question, Wuq, nullptr, nullptr, (float*)pWq, 1024, 256, 256);
    attn_kernel<<<dim3(P_DIM, B_DIM), blk>>>(question, passage, v);
    gemm_kernel<2><<<dim3(8192 / 64, 256 / 64), blk>>>(
        (const float*)pGcat, Wg + 256 * 512, nullptr, (const float*)pGcat,
        (float*)pCg, 8192, 256, 512);
    gemm_kernel<1><<<dim3(8192 / 64, 768 / 64), blk>>>(
        (const float*)pCg, w_ih, b_ih, nullptr, (float*)pGi, 8192, 768, 256);
    gru_kernel<<<128, 256>>>((const float*)pGi, w_hh, b_hh, out);
}